// round 7
// baseline (speedup 1.0000x reference)
#include <cuda_runtime.h>
#include <cstdint>

// DistEmb forward: out[i, :] = table[idx[i], :]
// table: [2e6, 128] fp32 (1 GB), idx: [1,048,576] int32, out: 512 MB fp32.
//
// R7: R4/R6 architecture (warp-per-row, float4/lane, batched gathers), but
// output stores switched __stcs -> __stwt (st.global.wt, write-through).
// The 512MB write stream no longer allocates lines in L2 at all, so L2
// (126MB) is dedicated to gathered table rows: ~26% of the 1M gathers are
// duplicate rows, and a larger table-resident L2 converts more of them into
// hits, cutting DRAM read traffic (bounded upside ~74MB ~= 11us).

static constexpr int EMB_F4        = 32;  // 128 floats = 32 float4
static constexpr int THREADS       = 256; // 8 warps / block
static constexpr int ROWS_PER_WARP = 8;

__global__ __launch_bounds__(THREADS)
void distemb_gather_kernel(const float4* __restrict__ table,
                           const int* __restrict__ idx,
                           float4* __restrict__ out,
                           int num_ids)
{
    const int gwarp = (blockIdx.x * THREADS + threadIdx.x) >> 5;
    const int lane  = threadIdx.x & 31;
    const int row0  = gwarp * ROWS_PER_WARP;
    if (row0 >= num_ids) return;

    if (row0 + ROWS_PER_WARP <= num_ids) {
        // Fast path: 8 rows, loads fully batched before stores.
        int src[ROWS_PER_WARP];
#pragma unroll
        for (int r = 0; r < ROWS_PER_WARP; r++)
            src[r] = __ldg(&idx[row0 + r]);        // warp-uniform broadcasts

        float4 v[ROWS_PER_WARP];
#pragma unroll
        for (int r = 0; r < ROWS_PER_WARP; r++)    // 8 independent LDG.128
            v[r] = __ldg(&table[(size_t)src[r] * EMB_F4 + lane]);

#pragma unroll
        for (int r = 0; r < ROWS_PER_WARP; r++)    // write-through: no L2 alloc
            __stwt(&out[(size_t)(row0 + r) * EMB_F4 + lane], v[r]);
    } else {
        for (int r = 0; row0 + r < num_ids; r++) {
            const int src = __ldg(&idx[row0 + r]);
            float4 v = __ldg(&table[(size_t)src * EMB_F4 + lane]);
            __stwt(&out[(size_t)(row0 + r) * EMB_F4 + lane], v);
        }
    }
}

extern "C" void kernel_launch(void* const* d_in, const int* in_sizes, int n_in,
                              void* d_out, int out_size)
{
    // Identify inputs by element count (table: 268,435,456 elems; idx: 1,048,576).
    const void* table_p = d_in[0];
    const void* idx_p   = d_in[1];
    int         idx_n   = in_sizes[1];
    if (n_in >= 2 && in_sizes[0] < in_sizes[1]) {
        table_p = d_in[1];
        idx_p   = d_in[0];
        idx_n   = in_sizes[0];
    }

    const float4* table = (const float4*)table_p;
    const int*    idx   = (const int*)idx_p;
    float4*       out   = (float4*)d_out;

    const int rows_per_block = (THREADS / 32) * ROWS_PER_WARP;  // 64
    const int grid = (idx_n + rows_per_block - 1) / rows_per_block;

    distemb_gather_kernel<<<grid, THREADS>>>(table, idx, out, idx_n);
}